// round 3
// baseline (speedup 1.0000x reference)
#include <cuda_runtime.h>
#include <cuda_bf16.h>
#include <stdint.h>

// FuzzyPooling: 2x2 stride-2 pooling with fuzzy membership selection.
// x: (32,64,128,128) fp32 -> out: (32,64,64,64) fp32
//
// mu1 = tri(v,1.5,1.5); mu2 = tri(v,3.0,1.5); mu3 == mu2 (identical
// constants), argmax takes first max -> sel = (s1 >= s2) ? mu1 : mu2.
// out = den==0 ? 0 : sum(mu*v*v)/sum(mu*v)
//
// Memberships are used only in (a) the s1 vs s2 comparison, (b) the
// num/den ratio, (c) the den==0 test — all invariant to a positive
// scale. So we use UNNORMALIZED memberships (x1.5):
//   t1(v) = max(min(v, 3-v), 0)
//   t2(v) = t1(v-1.5) = max(min(v-1.5, 4.5-v), 0)
// R3: IEEE div -> __fdividef (rcp+mul), reuse t=m*v for num and den.

#define H_IN   128
#define W_IN   128
#define HO     64
#define WO     64
#define BC     (32 * 64)
#define N_OUT  (BC * HO * WO)     // 8,388,608

__device__ __forceinline__ void memb(float v, float& u1, float& u2) {
    float w = v - 1.5f;
    u1 = fmaxf(fminf(v, 3.0f - v), 0.0f);
    u2 = fmaxf(fminf(w, 3.0f - w), 0.0f);
}

__device__ __forceinline__ float fuzzy_patch(float a, float b, float c, float d) {
    float m1a, m2a, m1b, m2b, m1c, m2c, m1d, m2d;
    memb(a, m1a, m2a);
    memb(b, m1b, m2b);
    memb(c, m1c, m2c);
    memb(d, m1d, m2d);

    float s1 = (m1a + m1b) + (m1c + m1d);
    float s2 = (m2a + m2b) + (m2c + m2d);
    bool pick1 = (s1 >= s2);

    float ma = pick1 ? m1a : m2a;
    float mb = pick1 ? m1b : m2b;
    float mc = pick1 ? m1c : m2c;
    float md = pick1 ? m1d : m2d;

    float ta = ma * a, tb = mb * b, tc = mc * c, td = md * d;
    float den = (ta + tb) + (tc + td);
    float num = fmaf(ta, a, fmaf(tb, b, fmaf(tc, c, td * d)));

    float r = __fdividef(num, den);          // approx div: rcp + mul
    return (den == 0.0f) ? 0.0f : r;         // NaN from 0/0 is discarded
}

__global__ __launch_bounds__(256)
void fuzzy_pool_kernel(const float* __restrict__ x, float* __restrict__ out) {
    // 4 outputs/thread: 4 independent float4 loads up front (MLP=4).
    int tid = blockIdx.x * blockDim.x + threadIdx.x;

    int wq  = tid & 15;            // quad index along Wo (WO/4 = 16)
    int ho  = (tid >> 4) & 63;     // output row
    int bc  = tid >> 10;           // plane

    const float4* base0 = reinterpret_cast<const float4*>(
        x + (size_t)bc * (H_IN * W_IN) + (2 * ho) * W_IN + 8 * wq);
    const float4* base1 = base0 + (W_IN / 4);

    float4 a0 = __ldcs(base0);
    float4 a1 = __ldcs(base0 + 1);
    float4 b0 = __ldcs(base1);
    float4 b1 = __ldcs(base1 + 1);

    float4 o;
    o.x = fuzzy_patch(a0.x, a0.y, b0.x, b0.y);
    o.y = fuzzy_patch(a0.z, a0.w, b0.z, b0.w);
    o.z = fuzzy_patch(a1.x, a1.y, b1.x, b1.y);
    o.w = fuzzy_patch(a1.z, a1.w, b1.z, b1.w);

    __stcs(reinterpret_cast<float4*>(
        out + (size_t)bc * (HO * WO) + ho * WO + 4 * wq), o);
}

extern "C" void kernel_launch(void* const* d_in, const int* in_sizes, int n_in,
                              void* d_out, int out_size) {
    const float* x = (const float*)d_in[0];
    float* out = (float*)d_out;
    int threads = 256;
    int total = N_OUT / 4;                  // 2,097,152
    int blocks = total / threads;           // 8192 exactly
    fuzzy_pool_kernel<<<blocks, threads>>>(x, out);
}